// round 11
// baseline (speedup 1.0000x reference)
#include <cuda_runtime.h>
#include <cuda_bf16.h>
#include <cstdint>

// ============================================================================
// Spectral pooling as two split-bf16 GEMMs on the legacy tensor-core path
// (mma.sync m16n8k16 — plain sm_100 target, no tcgen05).
//   out = A X A^T - B X B^T   (per batch, per channel)
// Stage 1: Ys[(k1,c)][(half,n2)-split] = W1[(half,k1)][n1-stk] * Xs[(c,n2)][n1-stk]
// Stage 2: out[k2][(k1,c)]             = W2[k2][(half,n2)-stk] * Ys
// Split bf16: v ~ v0 + v1; weights K-stacked [a0|a0|a1]; data dedup'd [x0|x1].
// R11: A operand pre-baked into mma-fragment layout in global memory and
// fetched with LDG.128 — removes A from the smem crossbar (cp.async writes +
// ldmatrix reads), which R8/R10 profiles showed co-limits the tensor pipe.
// ============================================================================

namespace {
constexpr int Hn = 256, Kc = 217, Bt = 16, Ch = 64;
constexpr int K1A = 768;    // stage-1 A K (3*256)
constexpr int K1B = 512;    // stage-1 B K (x0|x1)
constexpr int K2A = 1536;   // stage-2 A K (3*512)
constexpr int K2B = 1024;   // stage-2 B K (y0|y1)
constexpr int KB1 = K1A / 16;   // 48 k16-blocks
constexpr int KB2 = K2A / 16;   // 96
constexpr int NC1 = 16384;  // stage-1 N  (c*256 + n2)
constexpr int YR  = 14080;  // stage-2 N padded (110*128 >= 217*64=13888)
constexpr double PI_D = 3.14159265358979323846;
}

// A-operand fragment tables: [m16-block][k16-block][lane] -> uint4 {a0,a1,a2,a3}
__device__ uint4 g_W1f[32 * KB1 * 32];                  // rows>=434 stay 0
__device__ uint4 g_W2f[16 * KB2 * 32];                  // rows>=217 stay 0
__device__ __nv_bfloat16 g_Xs[(size_t)Bt * NC1 * K1B];  // stage-1 B operand
__device__ __nv_bfloat16 g_Ys[(size_t)Bt * YR * K2B];   // stage-2 B (pad rows 0)

#define SW128(x) ((x) ^ (((x) >> 3) & 0x70))

// ---------------- PTX helpers ------------------------------------------------
__device__ __forceinline__ uint32_t smem_u32(const void* p) {
    uint32_t a;
    asm("{ .reg .u64 t; cvta.to.shared.u64 t, %1; cvt.u32.u64 %0, t; }" : "=r"(a) : "l"(p));
    return a;
}
__device__ __forceinline__ void cp16(uint32_t dst, const void* src) {
    asm volatile("cp.async.cg.shared.global [%0], [%1], 16;" :: "r"(dst), "l"(src));
}
__device__ __forceinline__ void cp_commit() { asm volatile("cp.async.commit_group;"); }
template <int N>
__device__ __forceinline__ void cp_wait() {
    asm volatile("cp.async.wait_group %0;" :: "n"(N));
}
__device__ __forceinline__ void ldm_x4(uint32_t* r, uint32_t addr) {
    asm volatile("ldmatrix.sync.aligned.m8n8.x4.shared.b16 {%0,%1,%2,%3}, [%4];"
                 : "=r"(r[0]), "=r"(r[1]), "=r"(r[2]), "=r"(r[3]) : "r"(addr));
}
__device__ __forceinline__ void mma16816(float* c, const uint32_t* a,
                                         uint32_t b0, uint32_t b1) {
    asm volatile(
        "mma.sync.aligned.m16n8k16.row.col.f32.bf16.bf16.f32 "
        "{%0,%1,%2,%3}, {%4,%5,%6,%7}, {%8,%9}, {%0,%1,%2,%3};"
        : "+f"(c[0]), "+f"(c[1]), "+f"(c[2]), "+f"(c[3])
        : "r"(a[0]), "r"(a[1]), "r"(a[2]), "r"(a[3]), "r"(b0), "r"(b1));
}

// Scatter one bf16 into the fragment table at logical (row, col).
// m16n8k16 A-frag layout: reg j holds (r-half j&1 ? rows 8-15 : 0-7,
// k-half j>>1), lane = (r%8)*4 + (c%8)/2, bf16 slot = c%2.
__device__ __forceinline__ void frag_store(uint4* tab, int KB, int row, int col,
                                           __nv_bfloat16 v) {
    int mb = row >> 4, kb = col >> 4, r = row & 15, c = col & 15;
    int lane = ((r & 7) << 2) | ((c & 7) >> 1);
    int reg = (r >> 3) | ((c >> 3) << 1);
    __nv_bfloat16* p = (__nv_bfloat16*)tab;
    size_t idx = (((size_t)(mb * KB + kb) * 32 + lane) << 3) + (reg << 1) + (c & 1);
    p[idx] = v;
}

// ---------------- init: split-bf16 weights -> fragment tables ---------------
__global__ void sp_init() {
    int idx = blockIdx.x * blockDim.x + threadIdx.x;
    if (idx >= Kc * Hn) return;
    int k = idx / Hn, n = idx - (idx / Hn) * Hn;
    double ph = PI_D * ((double)k / (double)Kc - (double)n / (double)Hn);
    double D = (k == 0 && n == 0) ? 1.0 : sin(217.0 * ph) / (sin(ph) * 217.0);
    double ang = 2.0 * PI_D * (double)n / (double)Hn;
    float a = (float)(D * cos(ang));
    float b = (float)(D * sin(ang));
    __nv_bfloat16 a0 = __float2bfloat16(a);
    __nv_bfloat16 a1 = __float2bfloat16(a - __bfloat162float(a0));
    __nv_bfloat16 b0 = __float2bfloat16(b);
    __nv_bfloat16 b1 = __float2bfloat16(b - __bfloat162float(b0));
    float nb = -b;
    __nv_bfloat16 nb0 = __float2bfloat16(nb);
    __nv_bfloat16 nb1 = __float2bfloat16(nb - __bfloat162float(nb0));
    // W1 rows: A row k = [a0|a0|a1]; B row 217+k = [b0|b0|b1]
    frag_store(g_W1f, KB1, k, n, a0);
    frag_store(g_W1f, KB1, k, 256 + n, a0);
    frag_store(g_W1f, KB1, k, 512 + n, a1);
    frag_store(g_W1f, KB1, Kc + k, n, b0);
    frag_store(g_W1f, KB1, Kc + k, 256 + n, b0);
    frag_store(g_W1f, KB1, Kc + k, 512 + n, b1);
    // W2 row k: [a0 | -b0 | a0 | -b0 | a1 | -b1] over (half,n2) segments
    frag_store(g_W2f, KB2, k, n, a0);
    frag_store(g_W2f, KB2, k, 256 + n, nb0);
    frag_store(g_W2f, KB2, k, 512 + n, a0);
    frag_store(g_W2f, KB2, k, 768 + n, nb0);
    frag_store(g_W2f, KB2, k, 1024 + n, a1);
    frag_store(g_W2f, KB2, k, 1280 + n, nb1);
}

// ---------------- transpose+split: X -> Xs[b][c*256+n2][x0|x1] --------------
__global__ __launch_bounds__(256) void sp_transpose(const float* __restrict__ X) {
    __shared__ float tile[32][65];
    const int n2  = blockIdx.x;   // 0..255
    const int n1g = blockIdx.y;   // 0..7
    const int b   = blockIdx.z;
    const int t   = threadIdx.x;
    const float* src = X + ((size_t)(b * Hn + n1g * 32)) * NC1 + n2 * 64;
#pragma unroll
    for (int p = 0; p < 8; p++) {
        int idx = p * 256 + t;
        int r = idx >> 6, col = idx & 63;
        tile[r][col] = src[(size_t)r * NC1 + col];
    }
    __syncthreads();
    const int c = t >> 2, part = t & 3, i0 = part * 8;
    __nv_bfloat16* dst =
        g_Xs + ((size_t)b * NC1 + c * 256 + n2) * K1B + n1g * 32 + i0;
    __align__(16) __nv_bfloat16 h0[8], h1[8];
#pragma unroll
    for (int i = 0; i < 8; i++) {
        float v = tile[i0 + i][c];
        h0[i] = __float2bfloat16(v);
        h1[i] = __float2bfloat16(v - __bfloat162float(h0[i]));
    }
    *(uint4*)(dst)       = *(const uint4*)h0;
    *(uint4*)(dst + 256) = *(const uint4*)h1;
}

// ---------------- warp-MMA GEMM: CTA 256x128, warp m64n64, A via LDG --------
// SMEM: B double buffer 2 x 16KB = 32KB; stage-1 epilogue staging 72KB.
constexpr int BBUF = 16384;
constexpr int SMEM_GEMM = 73728;          // max(32KB, 256*288)
constexpr int EP_STRIDE = 288;

template <int STAGE>
__global__ __launch_bounds__(256, 1) void sp_gemm(float* __restrict__ out) {
    extern __shared__ char smem[];
    const uint32_t sb = smem_u32(smem);
    const int tid = threadIdx.x, lane = tid & 31, wid = tid >> 5;
    const int warp_m = wid >> 1, warp_n = wid & 1;   // 4 x 2 warp grid, m64n64
    const int mt = blockIdx.x, nt = blockIdx.y, b = blockIdx.z;

    constexpr int KTB = (STAGE == 1) ? K1B : K2B;
    constexpr int KB  = (STAGE == 1) ? KB1 : KB2;    // A k16-block count
    constexpr int NCH = ((STAGE == 1) ? K1A : K2A) / 64;   // 12 / 24
    constexpr int NB  = KTB / 64;                    // 8 / 16
    const uint4* __restrict__ Wf = ((STAGE == 1) ? g_W1f : g_W2f);
    const uint4* __restrict__ wbase =
        Wf + ((size_t)(mt * 16 + warp_m * 4) * KB) * 32 + lane;
    const __nv_bfloat16* Brow = ((STAGE == 1) ? (g_Xs + (size_t)b * NC1 * K1B)
                                              : (g_Ys + (size_t)b * YR * K2B))
                                + (size_t)(nt * 128) * KTB;

    float acc[4][8][4];
#pragma unroll
    for (int i = 0; i < 4; i++)
#pragma unroll
        for (int j = 0; j < 8; j++)
#pragma unroll
            for (int q = 0; q < 4; q++) acc[i][j][q] = 0.f;

    auto prefetchB = [&](int kc) {
        const int kb = (kc < NB) ? kc : kc - NB;    // dedup remap for B
        const uint32_t bbase = sb + (kc & 1) * BBUF;
        // B: 128 rows x 128B = 1024 16B slots; 4 per thread
#pragma unroll
        for (int p = 0; p < 4; p++) {
            int slot = p * 256 + tid;
            int r = slot >> 3, s = slot & 7;
            cp16(bbase + SW128(r * 128 + s * 16),
                 Brow + (size_t)r * KTB + kb * 64 + s * 8);
        }
        cp_commit();
    };

    const int brow = warp_n * 64 + (lane & 7) + ((lane >> 4) & 1) * 8;
    const int bkof = ((lane >> 3) & 1) * 16;

    prefetchB(0);
    for (int kc = 0; kc < NCH; kc++) {
        cp_wait<0>();
        __syncthreads();
        if (kc + 1 < NCH) prefetchB(kc + 1);
        const uint32_t bbase = sb + (kc & 1) * BBUF;
#pragma unroll
        for (int ks = 0; ks < 4; ks++) {
            const int kbg = kc * 4 + ks;            // A k16-block index
            uint4 af[4];
#pragma unroll
            for (int mi = 0; mi < 4; mi++)
                af[mi] = wbase[(mi * KB + kbg) * 32];   // LDG.128, coalesced
            uint32_t bf[4][4];
#pragma unroll
            for (int nj = 0; nj < 4; nj++)
                ldm_x4(bf[nj], bbase + SW128((brow + nj * 16) * 128 + ks * 32 + bkof));
#pragma unroll
            for (int mi = 0; mi < 4; mi++)
#pragma unroll
                for (int ni = 0; ni < 8; ni++)
                    mma16816(acc[mi][ni], (const uint32_t*)&af[mi],
                             bf[ni >> 1][(ni & 1) * 2], bf[ni >> 1][(ni & 1) * 2 + 1]);
        }
    }

    // ---------------- epilogue ----------------
    const int r0 = lane >> 2;          // c-frag rows r0, r0+8
    const int c0 = lane & 3;           // c-frag col-pair index
    if (STAGE == 1) {
        // Stage through smem -> coalesced 16B stores of each split segment.
        __nv_bfloat16* Yb = g_Ys + (size_t)b * YR * K2B;
#pragma unroll
        for (int seg = 0; seg < 2; seg++) {
            __syncthreads();
#pragma unroll
            for (int mi = 0; mi < 4; mi++) {
#pragma unroll
                for (int half_r = 0; half_r < 2; half_r++) {
                    const int row = warp_m * 64 + mi * 16 + r0 + half_r * 8;
#pragma unroll
                    for (int ni = 0; ni < 8; ni++) {
                        const int cp = warp_n * 32 + ni * 4 + c0;  // col pair 0..63
                        float v0 = acc[mi][ni][half_r * 2 + 0];
                        float v1 = acc[mi][ni][half_r * 2 + 1];
                        __nv_bfloat162 p;
                        if (seg == 0) {
                            p.x = __float2bfloat16(v0);
                            p.y = __float2bfloat16(v1);
                        } else {
                            __nv_bfloat16 h0a = __float2bfloat16(v0);
                            __nv_bfloat16 h0b = __float2bfloat16(v1);
                            p.x = __float2bfloat16(v0 - __bfloat162float(h0a));
                            p.y = __float2bfloat16(v1 - __bfloat162float(h0b));
                        }
                        *(__nv_bfloat162*)(smem + row * EP_STRIDE + cp * 4) = p;
                    }
                }
            }
            __syncthreads();
            // Coalesced copy: 256 rows x 16 x 16B units = 4096; 16 per thread.
#pragma unroll
            for (int p = 0; p < 16; p++) {
                const int u = p * 256 + tid;
                const int row = u >> 4, sl = u & 15;
                const int gr = mt * 256 + row;
                if (gr < 434) {
                    const int hf = (gr >= Kc) ? 1 : 0;
                    const int k1 = gr - hf * Kc;
                    const int gn = nt * 128 + sl * 8;
                    const int c = gn >> 8, n2 = gn & 255;
                    uint4 v = *(const uint4*)(smem + row * EP_STRIDE + sl * 16);
                    *(uint4*)(Yb + ((size_t)k1 * 64 + c) * K2B + hf * 256 + seg * 512 + n2) = v;
                }
            }
        }
    } else {
#pragma unroll
        for (int mi = 0; mi < 4; mi++) {
#pragma unroll
            for (int half_r = 0; half_r < 2; half_r++) {
                const int k2 = mt * 256 + warp_m * 64 + mi * 16 + r0 + half_r * 8;
                if (k2 >= Kc) continue;
#pragma unroll
                for (int ni = 0; ni < 8; ni++) {
                    const int gn = nt * 128 + warp_n * 64 + ni * 8 + 2 * c0;
                    const int k1 = gn >> 6, c = gn & 63;
                    if (k1 >= Kc) continue;
                    float2 v = make_float2(acc[mi][ni][half_r * 2 + 0],
                                           acc[mi][ni][half_r * 2 + 1]);
                    *(float2*)(out + ((size_t)(b * Kc + k1) * Kc + k2) * Ch + c) = v;
                }
            }
        }
    }
}

// ---------------------------------------------------------------------------
extern "C" void kernel_launch(void* const* d_in, const int* in_sizes, int n_in,
                              void* d_out, int out_size) {
    const float* X = (const float*)d_in[0];
    float* out = (float*)d_out;

    cudaFuncSetAttribute(sp_gemm<1>, cudaFuncAttributeMaxDynamicSharedMemorySize, SMEM_GEMM);
    cudaFuncSetAttribute(sp_gemm<2>, cudaFuncAttributeMaxDynamicSharedMemorySize, SMEM_GEMM);

    sp_init<<<(Kc * Hn + 255) / 256, 256>>>();
    sp_transpose<<<dim3(256, 8, Bt), 256>>>(X);
    sp_gemm<1><<<dim3(2, 128, Bt), 256, SMEM_GEMM>>>(nullptr);  // Ys = W1 * Xs^T
    sp_gemm<2><<<dim3(1, 110, Bt), 256, SMEM_GEMM>>>(out);      // out = W2 * Ys^T
}

// round 12
// speedup vs baseline: 1.4899x; 1.4899x over previous
#include <cuda_runtime.h>
#include <cuda_fp16.h>
#include <cstdint>

// ============================================================================
// Spectral pooling as two 2-term-split fp16 GEMMs on the legacy tensor path
// (mma.sync m16n8k16.f32.f16.f16.f32 — plain sm_100 target, no tcgen05).
//   out = A X A^T - B X B^T   (per batch, per channel)
// fp16 2-term split: data x = x0 + x1 (exact to 2^-22), weights truncated to
// fp16 (a0). K-stack A=[a0|a0], B=[x0|x1] computes a0*x exactly; error is
// (a - a0)*x ~ 2^-12 RMS per stage. K: stage1 512 (phys A 256), stage2 1024
// (phys A 512). GEMM core = R8 (m64n64, CTA 256x128, 2-buf cp.async).
// ============================================================================

namespace {
constexpr int Hn = 256, Kc = 217, Bt = 16, Ch = 64;
constexpr int K1B = 512;     // stage-1 B K (x0|x1), logical K too
constexpr int K1Ap = 256;    // stage-1 A physical K (a0 only)
constexpr int K2B = 1024;    // stage-2 B K (y0|y1), logical K too
constexpr int K2Ap = 512;    // stage-2 A physical K (w0 only)
constexpr int NC1 = 16384;   // stage-1 N  (c*256 + n2)
constexpr int YR  = 14080;   // stage-2 N padded (110*128 >= 217*64=13888)
constexpr double PI_D = 3.14159265358979323846;
}

__device__ __half g_W1s[512 * K1Ap];               // rows>=434 stay 0
__device__ __half g_W2s[256 * K2Ap];               // rows>=217 stay 0
__device__ __half g_Xs[(size_t)Bt * NC1 * K1B];    // stage-1 B operand
__device__ __half g_Ys[(size_t)Bt * YR * K2B];     // stage-2 B (pad rows 0)

#define SW128(x) ((x) ^ (((x) >> 3) & 0x70))

// ---------------- PTX helpers ------------------------------------------------
__device__ __forceinline__ uint32_t smem_u32(const void* p) {
    uint32_t a;
    asm("{ .reg .u64 t; cvta.to.shared.u64 t, %1; cvt.u32.u64 %0, t; }" : "=r"(a) : "l"(p));
    return a;
}
__device__ __forceinline__ void cp16(uint32_t dst, const void* src) {
    asm volatile("cp.async.cg.shared.global [%0], [%1], 16;" :: "r"(dst), "l"(src));
}
__device__ __forceinline__ void cp_commit() { asm volatile("cp.async.commit_group;"); }
template <int N>
__device__ __forceinline__ void cp_wait() {
    asm volatile("cp.async.wait_group %0;" :: "n"(N));
}
__device__ __forceinline__ void ldm_x4(uint32_t* r, uint32_t addr) {
    asm volatile("ldmatrix.sync.aligned.m8n8.x4.shared.b16 {%0,%1,%2,%3}, [%4];"
                 : "=r"(r[0]), "=r"(r[1]), "=r"(r[2]), "=r"(r[3]) : "r"(addr));
}
__device__ __forceinline__ void mma16816(float* c, const uint32_t* a,
                                         uint32_t b0, uint32_t b1) {
    asm volatile(
        "mma.sync.aligned.m16n8k16.row.col.f32.f16.f16.f32 "
        "{%0,%1,%2,%3}, {%4,%5,%6,%7}, {%8,%9}, {%0,%1,%2,%3};"
        : "+f"(c[0]), "+f"(c[1]), "+f"(c[2]), "+f"(c[3])
        : "r"(a[0]), "r"(a[1]), "r"(a[2]), "r"(a[3]), "r"(b0), "r"(b1));
}

// ---------------- init: fp16 weight tables ----------------------------------
__global__ void sp_init() {
    int idx = blockIdx.x * blockDim.x + threadIdx.x;
    if (idx >= Kc * Hn) return;
    int k = idx / Hn, n = idx - (idx / Hn) * Hn;
    double ph = PI_D * ((double)k / (double)Kc - (double)n / (double)Hn);
    double D = (k == 0 && n == 0) ? 1.0 : sin(217.0 * ph) / (sin(ph) * 217.0);
    double ang = 2.0 * PI_D * (double)n / (double)Hn;
    float a = (float)(D * cos(ang));
    float b = (float)(D * sin(ang));
    // W1 rows: row k = a0; row Kc+k = b0 (fp16-truncated weights)
    g_W1s[(size_t)k * K1Ap + n]        = __float2half(a);
    g_W1s[(size_t)(Kc + k) * K1Ap + n] = __float2half(b);
    // W2 row k: w0 = fp16([A | -B]) over (half,n2)
    g_W2s[(size_t)k * K2Ap + n]        = __float2half(a);
    g_W2s[(size_t)k * K2Ap + 256 + n]  = __float2half(-b);
}

// ---------------- transpose+split: X -> Xs[b][c*256+n2][x0|x1] --------------
__global__ __launch_bounds__(256) void sp_transpose(const float* __restrict__ X) {
    __shared__ float tile[32][65];
    const int n2  = blockIdx.x;   // 0..255
    const int n1g = blockIdx.y;   // 0..7
    const int b   = blockIdx.z;
    const int t   = threadIdx.x;
    const float* src = X + ((size_t)(b * Hn + n1g * 32)) * NC1 + n2 * 64;
#pragma unroll
    for (int p = 0; p < 8; p++) {
        int idx = p * 256 + t;
        int r = idx >> 6, col = idx & 63;
        tile[r][col] = src[(size_t)r * NC1 + col];
    }
    __syncthreads();
    const int c = t >> 2, part = t & 3, i0 = part * 8;
    __half* dst = g_Xs + ((size_t)b * NC1 + c * 256 + n2) * K1B + n1g * 32 + i0;
    __align__(16) __half h0[8], h1[8];
#pragma unroll
    for (int i = 0; i < 8; i++) {
        float v = tile[i0 + i][c];
        h0[i] = __float2half(v);
        h1[i] = __float2half(v - __half2float(h0[i]));
    }
    *(uint4*)(dst)       = *(const uint4*)h0;
    *(uint4*)(dst + 256) = *(const uint4*)h1;
}

// ---------------- warp-MMA GEMM: CTA 256x128, warp m64n64, double-buffered --
// SMEM per buf: A 256x128B (32KB) + B 128x128B (16KB) = 48KB; 2 bufs = 96KB.
constexpr int ST_BYTES = 49152;
constexpr int SMEM_GEMM = 2 * ST_BYTES;   // 98304
constexpr int EP_STRIDE = 288;

template <int STAGE>
__global__ __launch_bounds__(256, 1) void sp_gemm(float* __restrict__ out) {
    extern __shared__ char smem[];
    const uint32_t sb = smem_u32(smem);
    const int tid = threadIdx.x, lane = tid & 31, wid = tid >> 5;
    const int warp_m = wid >> 1, warp_n = wid & 1;   // 4 x 2 warp grid, m64n64
    const int mt = blockIdx.x, nt = blockIdx.y, b = blockIdx.z;

    constexpr int KTB = (STAGE == 1) ? K1B : K2B;    // B row stride (= logical K)
    constexpr int KTA = (STAGE == 1) ? K1Ap : K2Ap;  // A physical row stride
    constexpr int NCH = KTB / 64;                    // 8 / 16 logical chunks
    constexpr int NA  = KTA / 64;                    // 4 / 8 physical A chunks
    const __half* Arow = ((STAGE == 1) ? g_W1s : g_W2s) + (size_t)(mt * 256) * KTA;
    const __half* Brow = ((STAGE == 1) ? (g_Xs + (size_t)b * NC1 * K1B)
                                       : (g_Ys + (size_t)b * YR * K2B))
                         + (size_t)(nt * 128) * KTB;

    float acc[4][8][4];
#pragma unroll
    for (int i = 0; i < 4; i++)
#pragma unroll
        for (int j = 0; j < 8; j++)
#pragma unroll
            for (int q = 0; q < 4; q++) acc[i][j][q] = 0.f;

    auto prefetch = [&](int kc) {
        const int ka = (kc < NA) ? kc : kc - NA;    // A=[a0|a0]: re-read a0
        const uint32_t abase = sb + (kc & 1) * ST_BYTES;
        const uint32_t bbase = abase + 32768;
        // A: 256 rows x 128B = 2048 16B slots; 8 per thread
#pragma unroll
        for (int p = 0; p < 8; p++) {
            int slot = p * 256 + tid;
            int r = slot >> 3, s = slot & 7;
            cp16(abase + SW128(r * 128 + s * 16),
                 Arow + (size_t)r * KTA + ka * 64 + s * 8);
        }
        // B: 128 rows x 128B = 1024 slots; 4 per thread
#pragma unroll
        for (int p = 0; p < 4; p++) {
            int slot = p * 256 + tid;
            int r = slot >> 3, s = slot & 7;
            cp16(bbase + SW128(r * 128 + s * 16),
                 Brow + (size_t)r * KTB + kc * 64 + s * 8);
        }
        cp_commit();
    };

    const int arow = warp_m * 64 + (lane & 7) + ((lane >> 3) & 1) * 8;
    const int akof = ((lane >> 4) & 1) * 16;
    const int brow = warp_n * 64 + (lane & 7) + ((lane >> 4) & 1) * 8;
    const int bkof = ((lane >> 3) & 1) * 16;

    prefetch(0);
    for (int kc = 0; kc < NCH; kc++) {
        cp_wait<0>();
        __syncthreads();               // single barrier per chunk
        if (kc + 1 < NCH) prefetch(kc + 1);
        const uint32_t abase = sb + (kc & 1) * ST_BYTES;
        const uint32_t bbase = abase + 32768;
#pragma unroll
        for (int ks = 0; ks < 4; ks++) {
            const int kb0 = ks * 32;
            uint32_t af[4][4];
#pragma unroll
            for (int mi = 0; mi < 4; mi++)
                ldm_x4(af[mi], abase + SW128((arow + mi * 16) * 128 + kb0 + akof));
            uint32_t bf[4][4];
#pragma unroll
            for (int nj = 0; nj < 4; nj++)
                ldm_x4(bf[nj], bbase + SW128((brow + nj * 16) * 128 + kb0 + bkof));
#pragma unroll
            for (int mi = 0; mi < 4; mi++)
#pragma unroll
                for (int ni = 0; ni < 8; ni++)
                    mma16816(acc[mi][ni], af[mi],
                             bf[ni >> 1][(ni & 1) * 2], bf[ni >> 1][(ni & 1) * 2 + 1]);
        }
    }

    // ---------------- epilogue ----------------
    const int r0 = lane >> 2;          // c-frag rows r0, r0+8
    const int c0 = lane & 3;           // c-frag col-pair index
    if (STAGE == 1) {
        // Stage through smem -> coalesced 16B stores of each split segment.
        __half* Yb = g_Ys + (size_t)b * YR * K2B;
#pragma unroll
        for (int seg = 0; seg < 2; seg++) {
            __syncthreads();
#pragma unroll
            for (int mi = 0; mi < 4; mi++) {
#pragma unroll
                for (int half_r = 0; half_r < 2; half_r++) {
                    const int row = warp_m * 64 + mi * 16 + r0 + half_r * 8;
#pragma unroll
                    for (int ni = 0; ni < 8; ni++) {
                        const int cp = warp_n * 32 + ni * 4 + c0;  // col pair 0..63
                        float v0 = acc[mi][ni][half_r * 2 + 0];
                        float v1 = acc[mi][ni][half_r * 2 + 1];
                        __half2 p;
                        if (seg == 0) {
                            p.x = __float2half(v0);
                            p.y = __float2half(v1);
                        } else {
                            __half h0a = __float2half(v0);
                            __half h0b = __float2half(v1);
                            p.x = __float2half(v0 - __half2float(h0a));
                            p.y = __float2half(v1 - __half2float(h0b));
                        }
                        *(__half2*)(smem + row * EP_STRIDE + cp * 4) = p;
                    }
                }
            }
            __syncthreads();
            // Coalesced copy: 256 rows x 16 x 16B units = 4096; 16 per thread.
#pragma unroll
            for (int p = 0; p < 16; p++) {
                const int u = p * 256 + tid;
                const int row = u >> 4, sl = u & 15;
                const int gr = mt * 256 + row;
                if (gr < 434) {
                    const int hf = (gr >= Kc) ? 1 : 0;
                    const int k1 = gr - hf * Kc;
                    const int gn = nt * 128 + sl * 8;
                    const int c = gn >> 8, n2 = gn & 255;
                    uint4 v = *(const uint4*)(smem + row * EP_STRIDE + sl * 16);
                    *(uint4*)(Yb + ((size_t)k1 * 64 + c) * K2B + hf * 256 + seg * 512 + n2) = v;
                }
            }
        }
    } else {
#pragma unroll
        for (int mi = 0; mi < 4; mi++) {
#pragma unroll
            for (int half_r = 0; half_r < 2; half_r++) {
                const int k2 = mt * 256 + warp_m * 64 + mi * 16 + r0 + half_r * 8;
                if (k2 >= Kc) continue;
#pragma unroll
                for (int ni = 0; ni < 8; ni++) {
                    const int gn = nt * 128 + warp_n * 64 + ni * 8 + 2 * c0;
                    const int k1 = gn >> 6, c = gn & 63;
                    if (k1 >= Kc) continue;
                    float2 v = make_float2(acc[mi][ni][half_r * 2 + 0],
                                           acc[mi][ni][half_r * 2 + 1]);
                    *(float2*)(out + ((size_t)(b * Kc + k1) * Kc + k2) * Ch + c) = v;
                }
            }
        }
    }
}

// ---------------------------------------------------------------------------
extern "C" void kernel_launch(void* const* d_in, const int* in_sizes, int n_in,
                              void* d_out, int out_size) {
    const float* X = (const float*)d_in[0];
    float* out = (float*)d_out;

    cudaFuncSetAttribute(sp_gemm<1>, cudaFuncAttributeMaxDynamicSharedMemorySize, SMEM_GEMM);
    cudaFuncSetAttribute(sp_gemm<2>, cudaFuncAttributeMaxDynamicSharedMemorySize, SMEM_GEMM);

    sp_init<<<(Kc * Hn + 255) / 256, 256>>>();
    sp_transpose<<<dim3(256, 8, Bt), 256>>>(X);
    sp_gemm<1><<<dim3(2, 128, Bt), 256, SMEM_GEMM>>>(nullptr);  // Ys = W1 * Xs^T
    sp_gemm<2><<<dim3(1, 110, Bt), 256, SMEM_GEMM>>>(out);      // out = W2 * Ys^T
}

// round 13
// speedup vs baseline: 2.6879x; 1.8041x over previous
#include <cuda_runtime.h>
#include <cuda_fp16.h>
#include <cstdint>

// ============================================================================
// Spectral pooling as two plain-fp16 GEMMs (fp32 accumulate) on the legacy
// tensor path (mma.sync m16n8k16.f32.f16.f16.f32 — sm_100, no tcgen05).
//   out = A X A^T - B X B^T   (per batch, per channel)
// Stage 1: Ys[(k1,c)][(half,n2)] = W1[(half,k1)][n1] * Xs[(c,n2)][n1]   K=256
// Stage 2: out[k2][(k1,c)]       = W2[k2][(half,n2)] * Ys              K=512
// All operands fp16-rounded; fp32 accumulators. Error model (validated R12):
// each fp16 truncation adds ~1.2e-4 RMS incoherently -> total ~3.5e-4 < 1e-3.
// GEMM core: CTA 256x128, warp m64n64 (4x2), double-buffered cp.async.
// ============================================================================

namespace {
constexpr int Hn = 256, Kc = 217, Bt = 16, Ch = 64;
constexpr int K1 = 256;      // stage-1 K (n1)
constexpr int K2 = 512;      // stage-2 K (half,n2)
constexpr int NC1 = 16384;   // stage-1 N  (c*256 + n2)
constexpr int YR  = 14080;   // stage-2 N padded (110*128 >= 217*64=13888)
constexpr double PI_D = 3.14159265358979323846;
}

__device__ __half g_W1s[512 * K1];               // rows>=434 stay 0
__device__ __half g_W2s[256 * K2];               // rows>=217 stay 0
__device__ __half g_Xs[(size_t)Bt * NC1 * K1];   // stage-1 B operand
__device__ __half g_Ys[(size_t)Bt * YR * K2];    // stage-2 B (pad rows 0)

#define SW128(x) ((x) ^ (((x) >> 3) & 0x70))

// ---------------- PTX helpers ------------------------------------------------
__device__ __forceinline__ uint32_t smem_u32(const void* p) {
    uint32_t a;
    asm("{ .reg .u64 t; cvta.to.shared.u64 t, %1; cvt.u32.u64 %0, t; }" : "=r"(a) : "l"(p));
    return a;
}
__device__ __forceinline__ void cp16(uint32_t dst, const void* src) {
    asm volatile("cp.async.cg.shared.global [%0], [%1], 16;" :: "r"(dst), "l"(src));
}
__device__ __forceinline__ void cp_commit() { asm volatile("cp.async.commit_group;"); }
template <int N>
__device__ __forceinline__ void cp_wait() {
    asm volatile("cp.async.wait_group %0;" :: "n"(N));
}
__device__ __forceinline__ void ldm_x4(uint32_t* r, uint32_t addr) {
    asm volatile("ldmatrix.sync.aligned.m8n8.x4.shared.b16 {%0,%1,%2,%3}, [%4];"
                 : "=r"(r[0]), "=r"(r[1]), "=r"(r[2]), "=r"(r[3]) : "r"(addr));
}
__device__ __forceinline__ void mma16816(float* c, const uint32_t* a,
                                         uint32_t b0, uint32_t b1) {
    asm volatile(
        "mma.sync.aligned.m16n8k16.row.col.f32.f16.f16.f32 "
        "{%0,%1,%2,%3}, {%4,%5,%6,%7}, {%8,%9}, {%0,%1,%2,%3};"
        : "+f"(c[0]), "+f"(c[1]), "+f"(c[2]), "+f"(c[3])
        : "r"(a[0]), "r"(a[1]), "r"(a[2]), "r"(a[3]), "r"(b0), "r"(b1));
}

// ---------------- init: fp16 weight tables ----------------------------------
__global__ void sp_init() {
    int idx = blockIdx.x * blockDim.x + threadIdx.x;
    if (idx >= Kc * Hn) return;
    int k = idx / Hn, n = idx - (idx / Hn) * Hn;
    double ph = PI_D * ((double)k / (double)Kc - (double)n / (double)Hn);
    double D = (k == 0 && n == 0) ? 1.0 : sin(217.0 * ph) / (sin(ph) * 217.0);
    double ang = 2.0 * PI_D * (double)n / (double)Hn;
    float a = (float)(D * cos(ang));
    float b = (float)(D * sin(ang));
    // W1 rows: row k = A; row Kc+k = B
    g_W1s[(size_t)k * K1 + n]        = __float2half(a);
    g_W1s[(size_t)(Kc + k) * K1 + n] = __float2half(b);
    // W2 row k: [A | -B] over (half,n2)
    g_W2s[(size_t)k * K2 + n]        = __float2half(a);
    g_W2s[(size_t)k * K2 + 256 + n]  = __float2half(-b);
}

// ---------------- transpose: X -> Xs[b][c*256+n2][n1] fp16 ------------------
__global__ __launch_bounds__(256) void sp_transpose(const float* __restrict__ X) {
    __shared__ float tile[32][65];
    const int n2  = blockIdx.x;   // 0..255
    const int n1g = blockIdx.y;   // 0..7
    const int b   = blockIdx.z;
    const int t   = threadIdx.x;
    const float* src = X + ((size_t)(b * Hn + n1g * 32)) * NC1 + n2 * 64;
#pragma unroll
    for (int p = 0; p < 8; p++) {
        int idx = p * 256 + t;
        int r = idx >> 6, col = idx & 63;
        tile[r][col] = src[(size_t)r * NC1 + col];
    }
    __syncthreads();
    const int c = t >> 2, part = t & 3, i0 = part * 8;
    __half* dst = g_Xs + ((size_t)b * NC1 + c * 256 + n2) * K1 + n1g * 32 + i0;
    __align__(16) __half h0[8];
#pragma unroll
    for (int i = 0; i < 8; i++) h0[i] = __float2half(tile[i0 + i][c]);
    *(uint4*)(dst) = *(const uint4*)h0;
}

// ---------------- warp-MMA GEMM: CTA 256x128, warp m64n64, double-buffered --
// SMEM per buf: A 256x128B (32KB) + B 128x128B (16KB) = 48KB; 2 bufs = 96KB.
constexpr int ST_BYTES = 49152;
constexpr int SMEM_GEMM = 2 * ST_BYTES;   // 98304
constexpr int EP_STRIDE = 288;

template <int STAGE>
__global__ __launch_bounds__(256, 1) void sp_gemm(float* __restrict__ out) {
    extern __shared__ char smem[];
    const uint32_t sb = smem_u32(smem);
    const int tid = threadIdx.x, lane = tid & 31, wid = tid >> 5;
    const int warp_m = wid >> 1, warp_n = wid & 1;   // 4 x 2 warp grid, m64n64
    const int mt = blockIdx.x, nt = blockIdx.y, b = blockIdx.z;

    constexpr int KT  = (STAGE == 1) ? K1 : K2;      // K (row stride, both ops)
    constexpr int NCH = KT / 64;                     // 4 / 8 chunks
    const __half* Arow = ((STAGE == 1) ? g_W1s : g_W2s) + (size_t)(mt * 256) * KT;
    const __half* Brow = ((STAGE == 1) ? (g_Xs + (size_t)b * NC1 * K1)
                                       : (g_Ys + (size_t)b * YR * K2))
                         + (size_t)(nt * 128) * KT;

    float acc[4][8][4];
#pragma unroll
    for (int i = 0; i < 4; i++)
#pragma unroll
        for (int j = 0; j < 8; j++)
#pragma unroll
            for (int q = 0; q < 4; q++) acc[i][j][q] = 0.f;

    auto prefetch = [&](int kc) {
        const uint32_t abase = sb + (kc & 1) * ST_BYTES;
        const uint32_t bbase = abase + 32768;
        // A: 256 rows x 128B = 2048 16B slots; 8 per thread
#pragma unroll
        for (int p = 0; p < 8; p++) {
            int slot = p * 256 + tid;
            int r = slot >> 3, s = slot & 7;
            cp16(abase + SW128(r * 128 + s * 16),
                 Arow + (size_t)r * KT + kc * 64 + s * 8);
        }
        // B: 128 rows x 128B = 1024 slots; 4 per thread
#pragma unroll
        for (int p = 0; p < 4; p++) {
            int slot = p * 256 + tid;
            int r = slot >> 3, s = slot & 7;
            cp16(bbase + SW128(r * 128 + s * 16),
                 Brow + (size_t)r * KT + kc * 64 + s * 8);
        }
        cp_commit();
    };

    const int arow = warp_m * 64 + (lane & 7) + ((lane >> 3) & 1) * 8;
    const int akof = ((lane >> 4) & 1) * 16;
    const int brow = warp_n * 64 + (lane & 7) + ((lane >> 4) & 1) * 8;
    const int bkof = ((lane >> 3) & 1) * 16;

    prefetch(0);
    for (int kc = 0; kc < NCH; kc++) {
        cp_wait<0>();
        __syncthreads();               // single barrier per chunk
        if (kc + 1 < NCH) prefetch(kc + 1);
        const uint32_t abase = sb + (kc & 1) * ST_BYTES;
        const uint32_t bbase = abase + 32768;
#pragma unroll
        for (int ks = 0; ks < 4; ks++) {
            const int kb0 = ks * 32;
            uint32_t af[4][4];
#pragma unroll
            for (int mi = 0; mi < 4; mi++)
                ldm_x4(af[mi], abase + SW128((arow + mi * 16) * 128 + kb0 + akof));
            uint32_t bf[4][4];
#pragma unroll
            for (int nj = 0; nj < 4; nj++)
                ldm_x4(bf[nj], bbase + SW128((brow + nj * 16) * 128 + kb0 + bkof));
#pragma unroll
            for (int mi = 0; mi < 4; mi++)
#pragma unroll
                for (int ni = 0; ni < 8; ni++)
                    mma16816(acc[mi][ni], af[mi],
                             bf[ni >> 1][(ni & 1) * 2], bf[ni >> 1][(ni & 1) * 2 + 1]);
        }
    }

    // ---------------- epilogue ----------------
    const int r0 = lane >> 2;          // c-frag rows r0, r0+8
    const int c0 = lane & 3;           // c-frag col-pair index
    if (STAGE == 1) {
        // Stage through smem -> coalesced 16B fp16 stores.
        __half* Yb = g_Ys + (size_t)b * YR * K2;
        __syncthreads();
#pragma unroll
        for (int mi = 0; mi < 4; mi++) {
#pragma unroll
            for (int half_r = 0; half_r < 2; half_r++) {
                const int row = warp_m * 64 + mi * 16 + r0 + half_r * 8;
#pragma unroll
                for (int ni = 0; ni < 8; ni++) {
                    const int cp = warp_n * 32 + ni * 4 + c0;  // col pair 0..63
                    __half2 p;
                    p.x = __float2half(acc[mi][ni][half_r * 2 + 0]);
                    p.y = __float2half(acc[mi][ni][half_r * 2 + 1]);
                    *(__half2*)(smem + row * EP_STRIDE + cp * 4) = p;
                }
            }
        }
        __syncthreads();
        // Coalesced copy: 256 rows x 16 x 16B units = 4096; 16 per thread.
#pragma unroll
        for (int p = 0; p < 16; p++) {
            const int u = p * 256 + tid;
            const int row = u >> 4, sl = u & 15;
            const int gr = mt * 256 + row;
            if (gr < 434) {
                const int hf = (gr >= Kc) ? 1 : 0;
                const int k1 = gr - hf * Kc;
                const int gn = nt * 128 + sl * 8;
                const int c = gn >> 8, n2 = gn & 255;
                uint4 v = *(const uint4*)(smem + row * EP_STRIDE + sl * 16);
                *(uint4*)(Yb + ((size_t)k1 * 64 + c) * K2 + hf * 256 + n2) = v;
            }
        }
    } else {
#pragma unroll
        for (int mi = 0; mi < 4; mi++) {
#pragma unroll
            for (int half_r = 0; half_r < 2; half_r++) {
                const int k2 = mt * 256 + warp_m * 64 + mi * 16 + r0 + half_r * 8;
                if (k2 >= Kc) continue;
#pragma unroll
                for (int ni = 0; ni < 8; ni++) {
                    const int gn = nt * 128 + warp_n * 64 + ni * 8 + 2 * c0;
                    const int k1 = gn >> 6, c = gn & 63;
                    if (k1 >= Kc) continue;
                    float2 v = make_float2(acc[mi][ni][half_r * 2 + 0],
                                           acc[mi][ni][half_r * 2 + 1]);
                    *(float2*)(out + ((size_t)(b * Kc + k1) * Kc + k2) * Ch + c) = v;
                }
            }
        }
    }
}

// ---------------------------------------------------------------------------
extern "C" void kernel_launch(void* const* d_in, const int* in_sizes, int n_in,
                              void* d_out, int out_size) {
    const float* X = (const float*)d_in[0];
    float* out = (float*)d_out;

    cudaFuncSetAttribute(sp_gemm<1>, cudaFuncAttributeMaxDynamicSharedMemorySize, SMEM_GEMM);
    cudaFuncSetAttribute(sp_gemm<2>, cudaFuncAttributeMaxDynamicSharedMemorySize, SMEM_GEMM);

    sp_init<<<(Kc * Hn + 255) / 256, 256>>>();
    sp_transpose<<<dim3(256, 8, Bt), 256>>>(X);
    sp_gemm<1><<<dim3(2, 128, Bt), 256, SMEM_GEMM>>>(nullptr);  // Ys = W1 * Xs^T
    sp_gemm<2><<<dim3(1, 110, Bt), 256, SMEM_GEMM>>>(out);      // out = W2 * Ys^T
}